// round 11
// baseline (speedup 1.0000x reference)
#include <cuda_runtime.h>
#include <cuda_fp16.h>
#include <math.h>
#include <stdint.h>

#define SEQ     2048
#define HIDDEN  4544
#define NH      71
#define HD      64
#define QKV_OUT 4672
#define QKV_PAD 4736            // 37*128
#define DEN_PAD 4608            // 36*128
#define QDIM    4544

// Scaling: activations/weights stored as 64*x (fp16), GEMM acc = 4096*true.
// q stored 32*q (folds 1/8), k 64*k -> scores = 16384*true.
// P stored 64*P, v 64*v -> attn acc = 4096*(P.V); attn out stored 64*true.

// ---------------- scratch (device globals; no allocations allowed) ----------
__device__ float g_fused[SEQ * QKV_OUT];
__device__ float g_cos  [SEQ * 32];
__device__ float g_sin  [SEQ * 32];
__device__ __half g_xh [SEQ * HIDDEN];
__device__ __half g_wqh[QKV_PAD * HIDDEN];
__device__ __half g_wdh[DEN_PAD * HIDDEN];
__device__ __half g_ah [SEQ * HIDDEN];
__device__ __half g_qsh[NH * SEQ * HD];
__device__ __half g_ksh[SEQ * HD];
__device__ __half g_vsh[SEQ * HD];

// ================= portable PTX helpers (sm_80+; no tcgen05) ================
__device__ __forceinline__ uint32_t smem_to_u32(const void* p) {
    uint32_t a;
    asm("{ .reg .u64 t; cvta.to.shared.u64 t, %1; cvt.u32.u64 %0, t; }"
        : "=r"(a) : "l"(p));
    return a;
}
__device__ __forceinline__ void ldsm_x4(uint32_t& r0, uint32_t& r1,
                                        uint32_t& r2, uint32_t& r3, uint32_t addr) {
    asm volatile("ldmatrix.sync.aligned.m8n8.x4.shared.b16 {%0,%1,%2,%3}, [%4];"
                 : "=r"(r0), "=r"(r1), "=r"(r2), "=r"(r3) : "r"(addr));
}
__device__ __forceinline__ void ldsm_x4_t(uint32_t& r0, uint32_t& r1,
                                          uint32_t& r2, uint32_t& r3, uint32_t addr) {
    asm volatile("ldmatrix.sync.aligned.m8n8.x4.trans.shared.b16 {%0,%1,%2,%3}, [%4];"
                 : "=r"(r0), "=r"(r1), "=r"(r2), "=r"(r3) : "r"(addr));
}
__device__ __forceinline__ void mma16816(float* c, const uint32_t* a,
                                         uint32_t b0, uint32_t b1) {
    asm volatile("mma.sync.aligned.m16n8k16.row.col.f32.f16.f16.f32 "
                 "{%0,%1,%2,%3}, {%4,%5,%6,%7}, {%8,%9}, {%0,%1,%2,%3};"
                 : "+f"(c[0]), "+f"(c[1]), "+f"(c[2]), "+f"(c[3])
                 : "r"(a[0]), "r"(a[1]), "r"(a[2]), "r"(a[3]), "r"(b0), "r"(b1));
}
__device__ __forceinline__ void cp_async16(uint32_t sdst, const void* gsrc) {
    asm volatile("cp.async.cg.shared.global [%0], [%1], 16;" :: "r"(sdst), "l"(gsrc));
}
#define CP_COMMIT() asm volatile("cp.async.commit_group;" ::: "memory")
#define CP_WAIT(n)  asm volatile("cp.async.wait_group %0;" :: "n"(n) : "memory")

// ---------------- RoPE table (fp64 trig for accuracy) -----------------------
__global__ void rope_table_kernel() {
    int idx = blockIdx.x * blockDim.x + threadIdx.x;
    if (idx >= SEQ * 32) return;
    int s = idx >> 5, j = idx & 31;
    double inv = exp(-(double)j / 32.0 * log(10000.0));
    double ang = (double)s * inv;
    g_cos[idx] = (float)cos(ang);
    g_sin[idx] = (float)sin(ang);
}

// ---------------- fp32 -> fp16 (x64), vectorized (zero-pads tail rows) ------
__global__ void split4_h(const float4* __restrict__ src,
                         uint2* __restrict__ hi,
                         int total4, int src_total4)
{
    int i = blockIdx.x * blockDim.x + threadIdx.x;
    if (i >= total4) return;
    float4 v = (i < src_total4) ? src[i] : make_float4(0.f, 0.f, 0.f, 0.f);
    __half2 a = __floats2half2_rn(v.x * 64.f, v.y * 64.f);
    __half2 b = __floats2half2_rn(v.z * 64.f, v.w * 64.f);
    uint2 h;
    h.x = *reinterpret_cast<uint32_t*>(&a);
    h.y = *reinterpret_cast<uint32_t*>(&b);
    hi[i] = h;
}

// ---------------- prep: rope + scale + fp16 for q,k,v -----------------------
__global__ void prep_kernel() {
    int idx = blockIdx.x * blockDim.x + threadIdx.x;
    const int total = SEQ * (NH + 2) * 32;
    if (idx >= total) return;
    int j  = idx & 31;
    int t  = idx >> 5;
    int hh = t % (NH + 2);
    int s  = t / (NH + 2);
    size_t base = (size_t)s * QKV_OUT + hh * HD;
    float a = g_fused[base + j];
    float b = g_fused[base + j + 32];
    float o1, o2;
    if (hh <= NH) {
        float c  = g_cos[s * 32 + j];
        float sn = g_sin[s * 32 + j];
        o1 = a * c - b * sn;
        o2 = b * c + a * sn;
    } else {
        o1 = a; o2 = b;
    }
    if (hh < NH) {                        // q: scale 32 (folds 1/8 * 256)
        size_t doff = ((size_t)hh * SEQ + s) * HD;
        g_qsh[doff + j]      = __float2half_rn(o1 * 32.f);
        g_qsh[doff + j + 32] = __float2half_rn(o2 * 32.f);
    } else {                              // k or v: scale 64
        __half* dh = (hh == NH) ? g_ksh : g_vsh;
        size_t doff = (size_t)s * HD;
        dh[doff + j]      = __float2half_rn(o1 * 64.f);
        dh[doff + j + 32] = __float2half_rn(o2 * 64.f);
    }
}

// ---------------- mma.sync fp16 single-term GEMM ----------------------------
// C = A * B^T, both truncated fp16 (x64 scaled). 256x128 CTA, 512 threads
// (16 warps, 4Mx4N of 64x32 warptiles), 3-stage cp.async pipeline.
#define BM2 256
#define BN2 128
#define BKC 32
#define PIT 80                        // smem row pitch bytes (64B data)
#define A_ARR (BM2 * PIT)             // 20480
#define B_ARR (BN2 * PIT)             // 10240
#define STG2 (A_ARR + B_ARR)          // 30720
#define NSTG 3
#define GEMM_SMEM (NSTG * STG2)       // 92160

__global__ __launch_bounds__(512, 1) void gemm_mma(
    const __half* __restrict__ Ah, const __half* __restrict__ Bh,
    float* __restrict__ C, int N_real, int K)
{
    extern __shared__ __align__(128) char smem[];
    const int tid = threadIdx.x;
    const int wid = tid >> 5;
    const int lid = tid & 31;
    const int m0 = blockIdx.y * BM2;
    const int n0 = blockIdx.x * BN2;
    const int wm = (wid >> 2) * 64;
    const int wn = (wid & 3) * 32;
    const uint32_t sbase = smem_to_u32(smem);

#define LOAD_STAGE(s, k0) do {                                                  \
        uint32_t st_ = sbase + (s) * STG2;                                      \
        _Pragma("unroll")                                                       \
        for (int it_ = 0; it_ < 2; it_++) {          /* A: 256x32 */            \
            int id_ = it_ * 512 + tid;                                          \
            int r_ = id_ >> 2, ch_ = id_ & 3;                                   \
            cp_async16(st_ + r_ * PIT + ch_ * 16,                               \
                       Ah + (size_t)(m0 + r_) * K + (k0) + ch_ * 8);            \
        }                                                                       \
        {                                            /* B: 128x32 */            \
            int r_ = tid >> 2, ch_ = tid & 3;                                   \
            cp_async16(st_ + A_ARR + r_ * PIT + ch_ * 16,                       \
                       Bh + (size_t)(n0 + r_) * K + (k0) + ch_ * 8);            \
        }                                                                       \
    } while (0)

    float acc[4][4][4];
    #pragma unroll
    for (int i = 0; i < 4; i++)
        #pragma unroll
        for (int j = 0; j < 4; j++)
            #pragma unroll
            for (int e = 0; e < 4; e++) acc[i][j][e] = 0.0f;

    const int nchunk = K / BKC;
    LOAD_STAGE(0, 0);
    CP_COMMIT();
    LOAD_STAGE(1, BKC);
    CP_COMMIT();

    const int arow  = (lid & 7) | (((lid >> 3) & 1) << 3);
    const int acolh = (lid >> 4) * 8;
    const int brow  = (lid & 7) + ((lid >> 4) & 1) * 8;
    const int bcolh = ((lid >> 3) & 1) * 8;

    int cur = 0;
    for (int c = 0; c < nchunk; c++) {
        if (c + 1 < nchunk) { CP_WAIT(1); } else { CP_WAIT(0); }
        __syncthreads();
        if (c + 2 < nchunk) {
            int nxt = cur + 2; if (nxt >= NSTG) nxt -= NSTG;
            LOAD_STAGE(nxt, (c + 2) * BKC);
            CP_COMMIT();
        }

        const uint32_t sA = sbase + cur * STG2;
        const uint32_t sB = sA + A_ARR;

        #pragma unroll
        for (int kk = 0; kk < 2; kk++) {
            const int kc = kk * 16;
            uint32_t bh[2][4], af[4][4];
            #pragma unroll
            for (int j = 0; j < 2; j++) {
                uint32_t off = (uint32_t)((wn + j * 16 + brow) * PIT + (kc + bcolh) * 2);
                ldsm_x4(bh[j][0], bh[j][1], bh[j][2], bh[j][3], sB + off);
            }
            #pragma unroll
            for (int i = 0; i < 4; i++) {
                uint32_t off = (uint32_t)((wm + i * 16 + arow) * PIT + (kc + acolh) * 2);
                ldsm_x4(af[i][0], af[i][1], af[i][2], af[i][3], sA + off);
            }
            #pragma unroll
            for (int i = 0; i < 4; i++) {
                #pragma unroll
                for (int j = 0; j < 2; j++) {
                    mma16816(acc[i][j * 2 + 0], af[i], bh[j][0], bh[j][1]);
                    mma16816(acc[i][j * 2 + 1], af[i], bh[j][2], bh[j][3]);
                }
            }
        }
        cur++; if (cur >= NSTG) cur -= NSTG;
    }

    const float DS = 1.0f / 4096.0f;     // undo 64*64 input scaling
    const int gr = lid >> 2, tg = lid & 3;
    #pragma unroll
    for (int i = 0; i < 4; i++) {
        #pragma unroll
        for (int j = 0; j < 4; j++) {
            int col = n0 + wn + j * 8 + tg * 2;
            if (col < N_real) {
                int row = m0 + wm + i * 16 + gr;
                float2 v0 = make_float2(acc[i][j][0] * DS, acc[i][j][1] * DS);
                float2 v1 = make_float2(acc[i][j][2] * DS, acc[i][j][3] * DS);
                *reinterpret_cast<float2*>(&C[(size_t)row * N_real + col]) = v0;
                *reinterpret_cast<float2*>(&C[(size_t)(row + 8) * N_real + col]) = v1;
            }
        }
    }
#undef LOAD_STAGE
}

// ---------------- flash attention via mma.sync fp16 (MQA, causal) ------------
#define FROW_B 144
#define QARR_B (128 * FROW_B)
#define KV_STG (2 * QARR_B)                 // K, V
#define FA_SMEM (QARR_B + 2 * KV_STG)       // 92160

__global__ __launch_bounds__(256, 1) void flash_mma(
    const __half* __restrict__ qh,
    const __half* __restrict__ kh, const __half* __restrict__ vh,
    __half* __restrict__ oh)
{
    extern __shared__ __align__(128) char smem[];
    const int tid = threadIdx.x, wid = tid >> 5, lid = tid & 31;
    const int qt = blockIdx.x, h = blockIdx.y;
    const int q0 = qt * 128;
    const uint32_t sb = smem_to_u32(smem);
    const uint32_t sQ  = sb;
    const uint32_t sKV = sb + QARR_B;

    {
        #pragma unroll
        for (int i = 0; i < 4; i++) {
            int id = i * 256 + tid;
            int r = id >> 3, c = id & 7;
            cp_async16(sQ + r * FROW_B + c * 16,
                       qh + ((size_t)h * SEQ + q0 + r) * HD + c * 8);
        }
    }
    const __half* kvsrc[2] = {kh, vh};
#define LOAD_KV(s, kt_) do {                                                   \
        _Pragma("unroll")                                                      \
        for (int i_ = 0; i_ < 8; i_++) {                                       \
            int id_ = i_ * 256 + tid;                                          \
            int a_ = id_ >> 10, w_ = id_ & 1023, r_ = w_ >> 3, c_ = w_ & 7;    \
            cp_async16(sKV + (s) * KV_STG + a_ * QARR_B + r_ * FROW_B + c_ * 16, \
                       kvsrc[a_] + ((size_t)((kt_) * 128 + r_)) * HD + c_ * 8); \
        }                                                                      \
    } while (0)
    LOAD_KV(0, 0);
    CP_COMMIT();
    CP_WAIT(0);
    __syncthreads();

    const int arow  = (lid & 7) | (((lid >> 3) & 1) << 3);
    const int acolh = (lid >> 4) * 8;
    const int brow  = (lid & 7) + ((lid >> 4) & 1) * 8;
    const int bcolh = ((lid >> 3) & 1) * 8;

    uint32_t aq[4][4];
    #pragma unroll
    for (int k = 0; k < 4; k++) {
        uint32_t off = (uint32_t)((wid * 16 + arow) * FROW_B + (k * 16 + acolh) * 2);
        ldsm_x4(aq[k][0], aq[k][1], aq[k][2], aq[k][3], sQ + off);
    }

    float acc[8][4];
    #pragma unroll
    for (int g = 0; g < 8; g++)
        #pragma unroll
        for (int e = 0; e < 4; e++) acc[g][e] = 0.0f;
    float m0 = -1e30f, m1 = -1e30f, l0 = 0.0f, l1 = 0.0f;
    const int row0 = q0 + wid * 16 + (lid >> 2);
    const float SC = 1.0f / 16384.0f;   // undo 32*64 q/k scaling (incl 1/8)

    const int nkv = qt + 1;
    for (int kt = 0; kt < nkv; kt++) {
        const int cur = kt & 1;
        if (kt + 1 < nkv) { LOAD_KV(cur ^ 1, kt + 1); CP_COMMIT(); }
        const uint32_t sK = sKV + cur * KV_STG;
        const uint32_t sV = sK + QARR_B;

        float sc[16][4];
        #pragma unroll
        for (int t = 0; t < 16; t++)
            #pragma unroll
            for (int e = 0; e < 4; e++) sc[t][e] = 0.0f;

        #pragma unroll
        for (int j2 = 0; j2 < 8; j2++) {
            #pragma unroll
            for (int k = 0; k < 4; k++) {
                uint32_t off = (uint32_t)((j2 * 16 + brow) * FROW_B + (k * 16 + bcolh) * 2);
                uint32_t b0, b1, b2, b3;
                ldsm_x4(b0, b1, b2, b3, sK + off);
                mma16816(sc[j2 * 2],     aq[k], b0, b1);
                mma16816(sc[j2 * 2 + 1], aq[k], b2, b3);
            }
        }

        #pragma unroll
        for (int t = 0; t < 16; t++)
            #pragma unroll
            for (int e = 0; e < 4; e++) sc[t][e] *= SC;

        if (kt == qt) {
            #pragma unroll
            for (int t = 0; t < 16; t++) {
                int colb = kt * 128 + t * 8 + (lid & 3) * 2;
                if (colb     > row0)     sc[t][0] = -1e30f;
                if (colb + 1 > row0)     sc[t][1] = -1e30f;
                if (colb     > row0 + 8) sc[t][2] = -1e30f;
                if (colb + 1 > row0 + 8) sc[t][3] = -1e30f;
            }
        }

        float mn0 = m0, mn1 = m1;
        #pragma unroll
        for (int t = 0; t < 16; t++) {
            mn0 = fmaxf(mn0, fmaxf(sc[t][0], sc[t][1]));
            mn1 = fmaxf(mn1, fmaxf(sc[t][2], sc[t][3]));
        }
        mn0 = fmaxf(mn0, __shfl_xor_sync(0xffffffffu, mn0, 1));
        mn0 = fmaxf(mn0, __shfl_xor_sync(0xffffffffu, mn0, 2));
        mn1 = fmaxf(mn1, __shfl_xor_sync(0xffffffffu, mn1, 1));
        mn1 = fmaxf(mn1, __shfl_xor_sync(0xffffffffu, mn1, 2));
        float corr0 = __expf(m0 - mn0);
        float corr1 = __expf(m1 - mn1);

        uint32_t phi[16][2];
        float ls0 = 0.0f, ls1 = 0.0f;
        #pragma unroll
        for (int t = 0; t < 16; t++) {
            float p0 = __expf(sc[t][0] - mn0);
            float p1 = __expf(sc[t][1] - mn0);
            float p2 = __expf(sc[t][2] - mn1);
            float p3 = __expf(sc[t][3] - mn1);
            ls0 += p0 + p1;  ls1 += p2 + p3;
            __half2 ph0 = __floats2half2_rn(p0 * 64.f, p1 * 64.f);
            __half2 ph1 = __floats2half2_rn(p2 * 64.f, p3 * 64.f);
            phi[t][0] = *reinterpret_cast<uint32_t*>(&ph0);
            phi[t][1] = *reinterpret_cast<uint32_t*>(&ph1);
        }
        ls0 += __shfl_xor_sync(0xffffffffu, ls0, 1);
        ls0 += __shfl_xor_sync(0xffffffffu, ls0, 2);
        ls1 += __shfl_xor_sync(0xffffffffu, ls1, 1);
        ls1 += __shfl_xor_sync(0xffffffffu, ls1, 2);
        l0 = l0 * corr0 + ls0;  l1 = l1 * corr1 + ls1;
        m0 = mn0;  m1 = mn1;
        #pragma unroll
        for (int g = 0; g < 8; g++) {
            acc[g][0] *= corr0; acc[g][1] *= corr0;
            acc[g][2] *= corr1; acc[g][3] *= corr1;
        }

        #pragma unroll
        for (int k = 0; k < 8; k++) {
            uint32_t ph_[4] = {phi[k * 2][0], phi[k * 2][1], phi[k * 2 + 1][0], phi[k * 2 + 1][1]};
            #pragma unroll
            for (int g = 0; g < 4; g++) {
                uint32_t off = (uint32_t)((k * 16 + (lid & 15)) * FROW_B +
                                          (g * 16 + ((lid >> 4) & 1) * 8) * 2);
                uint32_t v0, v1, v2, v3;
                ldsm_x4_t(v0, v1, v2, v3, sV + off);
                mma16816(acc[g * 2],     ph_, v0, v1);
                mma16816(acc[g * 2 + 1], ph_, v2, v3);
            }
        }

        if (kt + 1 < nkv) CP_WAIT(0);
        __syncthreads();
    }
#undef LOAD_KV

    // out' = 64 * true_out (feeds dense GEMM A-side): acc = 4096*P.V, /l, *64
    float inv0 = 1.0f / (64.0f * l0), inv1 = 1.0f / (64.0f * l1);
    #pragma unroll
    for (int g = 0; g < 8; g++) {
        int col = h * HD + g * 8 + (lid & 3) * 2;
        int r = q0 + wid * 16 + (lid >> 2);
        __half2 h0 = __floats2half2_rn(acc[g][0] * inv0, acc[g][1] * inv0);
        __half2 h1 = __floats2half2_rn(acc[g][2] * inv1, acc[g][3] * inv1);
        *reinterpret_cast<uint32_t*>(&oh[(size_t)r * QDIM + col]) =
            *reinterpret_cast<uint32_t*>(&h0);
        *reinterpret_cast<uint32_t*>(&oh[(size_t)(r + 8) * QDIM + col]) =
            *reinterpret_cast<uint32_t*>(&h1);
    }
}

// ---------------- launch ----------------------------------------------------
extern "C" void kernel_launch(void* const* d_in, const int* in_sizes, int n_in,
                              void* d_out, int out_size)
{
    const float* x       = (const float*)d_in[0];
    const float* qkv_w   = (const float*)d_in[1];
    const float* dense_w = (const float*)d_in[2];
    float* out = (float*)d_out;

    float* fused; cudaGetSymbolAddress((void**)&fused, g_fused);
    __half *xh, *wqh, *wdh, *ah, *qsh, *ksh, *vsh;
    cudaGetSymbolAddress((void**)&xh,  g_xh);
    cudaGetSymbolAddress((void**)&wqh, g_wqh);
    cudaGetSymbolAddress((void**)&wdh, g_wdh);
    cudaGetSymbolAddress((void**)&ah,  g_ah);
    cudaGetSymbolAddress((void**)&qsh, g_qsh);
    cudaGetSymbolAddress((void**)&ksh, g_ksh);
    cudaGetSymbolAddress((void**)&vsh, g_vsh);

    cudaFuncSetAttribute(gemm_mma,
                         cudaFuncAttributeMaxDynamicSharedMemorySize, GEMM_SMEM);
    cudaFuncSetAttribute(flash_mma,
                         cudaFuncAttributeMaxDynamicSharedMemorySize, FA_SMEM);

    // 1. RoPE table
    rope_table_kernel<<<(SEQ * 32 + 255) / 256, 256>>>();

    // 2. fp16 conversions (x64 scale)
    {
        int t4 = SEQ * HIDDEN / 4;
        split4_h<<<(t4 + 255) / 256, 256>>>(
            (const float4*)x, (uint2*)xh, t4, t4);
        int tw4 = QKV_PAD * HIDDEN / 4, sw4 = QKV_OUT * HIDDEN / 4;
        split4_h<<<(tw4 + 255) / 256, 256>>>(
            (const float4*)qkv_w, (uint2*)wqh, tw4, sw4);
        int td4 = DEN_PAD * HIDDEN / 4, sd4 = HIDDEN * HIDDEN / 4;
        split4_h<<<(td4 + 255) / 256, 256>>>(
            (const float4*)dense_w, (uint2*)wdh, td4, sd4);
    }

    // 3. QKV GEMM (single-term fp16)
    {
        dim3 grid(QKV_PAD / BN2, SEQ / BM2);
        gemm_mma<<<grid, 512, GEMM_SMEM>>>(xh, wqh, fused, QKV_OUT, HIDDEN);
    }

    // 4. prep: rope + scale + fp16 of q, k, v
    {
        int total = SEQ * (NH + 2) * 32;
        prep_kernel<<<(total + 255) / 256, 256>>>();
    }

    // 5. flash attention -> fp16 activations (pre-scaled x64)
    {
        dim3 grid(SEQ / 128, NH);
        flash_mma<<<grid, 256, FA_SMEM>>>(qsh, ksh, vsh, ah);
    }

    // 6. dense GEMM (single-term fp16) -> out
    {
        dim3 grid(DEN_PAD / BN2, SEQ / BM2);
        gemm_mma<<<grid, 512, GEMM_SMEM>>>(ah, wdh, out, HIDDEN, HIDDEN);
    }
}

// round 14
// speedup vs baseline: 1.1609x; 1.1609x over previous
#include <cuda_runtime.h>
#include <cuda_fp16.h>
#include <math.h>
#include <stdint.h>

#define SEQ     2048
#define HIDDEN  4544
#define NH      71
#define HD      64
#define QKV_OUT 4672
#define QKV_PAD 4736            // 37*128
#define DEN_PAD 4608            // 36*128
#define QDIM    4544

// Scaling: activations/weights stored as 64*x (fp16), GEMM acc = 4096*true.
// fused (qkv gemm out) stored as 64*true fp16.
// q stored 32*q (folds 1/8), k 64*k -> scores = 16384*true.
// P stored 64*P, v 64*v -> attn acc = 4096*(P.V); attn out stored 64*true.

// ---------------- scratch (device globals; no allocations allowed) ----------
__device__ __half g_fused_h[SEQ * QKV_OUT];
__device__ float g_cos  [SEQ * 32];
__device__ float g_sin  [SEQ * 32];
__device__ __half g_xh [SEQ * HIDDEN];
__device__ __half g_wqh[QKV_PAD * HIDDEN];
__device__ __half g_wdh[DEN_PAD * HIDDEN];
__device__ __half g_ah [SEQ * HIDDEN];
__device__ __half g_qsh[NH * SEQ * HD];
__device__ __half g_ksh[SEQ * HD];
__device__ __half g_vsh[SEQ * HD];

// ================= portable PTX helpers (sm_80+; no tcgen05) ================
__device__ __forceinline__ uint32_t smem_to_u32(const void* p) {
    uint32_t a;
    asm("{ .reg .u64 t; cvta.to.shared.u64 t, %1; cvt.u32.u64 %0, t; }"
        : "=r"(a) : "l"(p));
    return a;
}
__device__ __forceinline__ void ldsm_x4(uint32_t& r0, uint32_t& r1,
                                        uint32_t& r2, uint32_t& r3, uint32_t addr) {
    asm volatile("ldmatrix.sync.aligned.m8n8.x4.shared.b16 {%0,%1,%2,%3}, [%4];"
                 : "=r"(r0), "=r"(r1), "=r"(r2), "=r"(r3) : "r"(addr));
}
__device__ __forceinline__ void ldsm_x4_t(uint32_t& r0, uint32_t& r1,
                                          uint32_t& r2, uint32_t& r3, uint32_t addr) {
    asm volatile("ldmatrix.sync.aligned.m8n8.x4.trans.shared.b16 {%0,%1,%2,%3}, [%4];"
                 : "=r"(r0), "=r"(r1), "=r"(r2), "=r"(r3) : "r"(addr));
}
__device__ __forceinline__ void mma16816(float* c, const uint32_t* a,
                                         uint32_t b0, uint32_t b1) {
    asm volatile("mma.sync.aligned.m16n8k16.row.col.f32.f16.f16.f32 "
                 "{%0,%1,%2,%3}, {%4,%5,%6,%7}, {%8,%9}, {%0,%1,%2,%3};"
                 : "+f"(c[0]), "+f"(c[1]), "+f"(c[2]), "+f"(c[3])
                 : "r"(a[0]), "r"(a[1]), "r"(a[2]), "r"(a[3]), "r"(b0), "r"(b1));
}
__device__ __forceinline__ void cp_async16(uint32_t sdst, const void* gsrc) {
    asm volatile("cp.async.cg.shared.global [%0], [%1], 16;" :: "r"(sdst), "l"(gsrc));
}
#define CP_COMMIT() asm volatile("cp.async.commit_group;" ::: "memory")
#define CP_WAIT(n)  asm volatile("cp.async.wait_group %0;" :: "n"(n) : "memory")

// ---------------- RoPE table (fp64 trig for accuracy) -----------------------
__global__ void rope_table_kernel() {
    int idx = blockIdx.x * blockDim.x + threadIdx.x;
    if (idx >= SEQ * 32) return;
    int s = idx >> 5, j = idx & 31;
    double inv = exp(-(double)j / 32.0 * log(10000.0));
    double ang = (double)s * inv;
    g_cos[idx] = (float)cos(ang);
    g_sin[idx] = (float)sin(ang);
}

// ---------------- merged fp32 -> fp16 (x64) conversion, 3 segments ----------
__global__ void convert_all(const float4* __restrict__ x,
                            const float4* __restrict__ wq,
                            const float4* __restrict__ wd,
                            uint2* __restrict__ xh,
                            uint2* __restrict__ wqh,
                            uint2* __restrict__ wdh,
                            int n0, int n1, int n2, int s1, int s2)
{
    int i = blockIdx.x * blockDim.x + threadIdx.x;
    const float4* src; uint2* dst; int idx, slim;
    if (i < n0)            { src = x;  dst = xh;  idx = i;            slim = n0; }
    else if (i < n0 + n1)  { src = wq; dst = wqh; idx = i - n0;       slim = s1; }
    else if (i < n0 + n1 + n2) { src = wd; dst = wdh; idx = i - n0 - n1; slim = s2; }
    else return;
    float4 v = (idx < slim) ? src[idx] : make_float4(0.f, 0.f, 0.f, 0.f);
    __half2 a = __floats2half2_rn(v.x * 64.f, v.y * 64.f);
    __half2 b = __floats2half2_rn(v.z * 64.f, v.w * 64.f);
    uint2 h;
    h.x = *reinterpret_cast<uint32_t*>(&a);
    h.y = *reinterpret_cast<uint32_t*>(&b);
    dst[idx] = h;
}

// ---------------- prep: rope + scale + fp16 for q,k,v (reads half fused) ----
__global__ void prep_kernel() {
    int idx = blockIdx.x * blockDim.x + threadIdx.x;
    const int total = SEQ * (NH + 2) * 32;
    if (idx >= total) return;
    int j  = idx & 31;
    int t  = idx >> 5;
    int hh = t % (NH + 2);
    int s  = t / (NH + 2);
    size_t base = (size_t)s * QKV_OUT + hh * HD;
    float a = __half2float(g_fused_h[base + j]);        // 64*true
    float b = __half2float(g_fused_h[base + j + 32]);
    float o1, o2;
    if (hh <= NH) {
        float c  = g_cos[s * 32 + j];
        float sn = g_sin[s * 32 + j];
        o1 = a * c - b * sn;
        o2 = b * c + a * sn;
    } else {
        o1 = a; o2 = b;
    }
    if (hh < NH) {                        // q: 32*true (folds 1/8 into scale)
        size_t doff = ((size_t)hh * SEQ + s) * HD;
        g_qsh[doff + j]      = __float2half_rn(o1 * 0.5f);
        g_qsh[doff + j + 32] = __float2half_rn(o2 * 0.5f);
    } else {                              // k or v: 64*true
        __half* dh = (hh == NH) ? g_ksh : g_vsh;
        size_t doff = (size_t)s * HD;
        dh[doff + j]      = __float2half_rn(o1);
        dh[doff + j + 32] = __float2half_rn(o2);
    }
}

// ---------------- mma.sync fp16 single-term GEMM ----------------------------
// C = A * B^T (x64-scaled fp16). 256x128 CTA, 512 threads, K-chunk 64,
// 3-stage cp.async. Output templated: half (x64 fused) or float (final).
#define BM2 256
#define BN2 128
#define BKC 64
#define PIT 144                       // smem row pitch bytes (128B data + 16)
#define A_ARR (BM2 * PIT)             // 36864
#define B_ARR (BN2 * PIT)             // 18432
#define STG2 (A_ARR + B_ARR)          // 55296
#define NSTG 3
#define GEMM_SMEM (NSTG * STG2)       // 165888

template <typename OutT>
__global__ __launch_bounds__(512, 1) void gemm_mma(
    const __half* __restrict__ Ah, const __half* __restrict__ Bh,
    OutT* __restrict__ C, int N_real, int K)
{
    extern __shared__ __align__(128) char smem[];
    const int tid = threadIdx.x;
    const int wid = tid >> 5;
    const int lid = tid & 31;
    const int m0 = blockIdx.y * BM2;
    const int n0 = blockIdx.x * BN2;
    const int wm = (wid >> 2) * 64;
    const int wn = (wid & 3) * 32;
    const uint32_t sbase = smem_to_u32(smem);

#define LOAD_STAGE(s, k0) do {                                                  \
        uint32_t st_ = sbase + (s) * STG2;                                      \
        _Pragma("unroll")                                                       \
        for (int it_ = 0; it_ < 4; it_++) {          /* A: 256x64 */            \
            int id_ = it_ * 512 + tid;                                          \
            int r_ = id_ >> 3, ch_ = id_ & 7;                                   \
            cp_async16(st_ + r_ * PIT + ch_ * 16,                               \
                       Ah + (size_t)(m0 + r_) * K + (k0) + ch_ * 8);            \
        }                                                                       \
        _Pragma("unroll")                                                       \
        for (int it_ = 0; it_ < 2; it_++) {          /* B: 128x64 */            \
            int id_ = it_ * 512 + tid;                                          \
            int r_ = id_ >> 3, ch_ = id_ & 7;                                   \
            cp_async16(st_ + A_ARR + r_ * PIT + ch_ * 16,                       \
                       Bh + (size_t)(n0 + r_) * K + (k0) + ch_ * 8);            \
        }                                                                       \
    } while (0)

    float acc[4][4][4];
    #pragma unroll
    for (int i = 0; i < 4; i++)
        #pragma unroll
        for (int j = 0; j < 4; j++)
            #pragma unroll
            for (int e = 0; e < 4; e++) acc[i][j][e] = 0.0f;

    const int nchunk = K / BKC;
    LOAD_STAGE(0, 0);
    CP_COMMIT();
    LOAD_STAGE(1, BKC);
    CP_COMMIT();

    const int arow  = (lid & 7) | (((lid >> 3) & 1) << 3);
    const int acolh = (lid >> 4) * 8;
    const int brow  = (lid & 7) + ((lid >> 4) & 1) * 8;
    const int bcolh = ((lid >> 3) & 1) * 8;

    int cur = 0;
    for (int c = 0; c < nchunk; c++) {
        if (c + 1 < nchunk) { CP_WAIT(1); } else { CP_WAIT(0); }
        __syncthreads();
        if (c + 2 < nchunk) {
            int nxt = cur + 2; if (nxt >= NSTG) nxt -= NSTG;
            LOAD_STAGE(nxt, (c + 2) * BKC);
            CP_COMMIT();
        }

        const uint32_t sA = sbase + cur * STG2;
        const uint32_t sB = sA + A_ARR;

        #pragma unroll
        for (int kk = 0; kk < 4; kk++) {
            const int kc = kk * 16;
            uint32_t bh[2][4], af[4][4];
            #pragma unroll
            for (int j = 0; j < 2; j++) {
                uint32_t off = (uint32_t)((wn + j * 16 + brow) * PIT + (kc + bcolh) * 2);
                ldsm_x4(bh[j][0], bh[j][1], bh[j][2], bh[j][3], sB + off);
            }
            #pragma unroll
            for (int i = 0; i < 4; i++) {
                uint32_t off = (uint32_t)((wm + i * 16 + arow) * PIT + (kc + acolh) * 2);
                ldsm_x4(af[i][0], af[i][1], af[i][2], af[i][3], sA + off);
            }
            #pragma unroll
            for (int i = 0; i < 4; i++) {
                #pragma unroll
                for (int j = 0; j < 2; j++) {
                    mma16816(acc[i][j * 2 + 0], af[i], bh[j][0], bh[j][1]);
                    mma16816(acc[i][j * 2 + 1], af[i], bh[j][2], bh[j][3]);
                }
            }
        }
        cur++; if (cur >= NSTG) cur -= NSTG;
    }

    const int gr = lid >> 2, tg = lid & 3;
    #pragma unroll
    for (int i = 0; i < 4; i++) {
        #pragma unroll
        for (int j = 0; j < 4; j++) {
            int col = n0 + wn + j * 8 + tg * 2;
            if (col < N_real) {
                int row = m0 + wm + i * 16 + gr;
                if constexpr (sizeof(OutT) == 2) {
                    // fused output: 64*true = acc * 2^-6
                    const float DS = 1.0f / 64.0f;
                    __half2 p0 = __floats2half2_rn(acc[i][j][0] * DS, acc[i][j][1] * DS);
                    __half2 p1 = __floats2half2_rn(acc[i][j][2] * DS, acc[i][j][3] * DS);
                    *reinterpret_cast<uint32_t*>(&C[(size_t)row * N_real + col]) =
                        *reinterpret_cast<uint32_t*>(&p0);
                    *reinterpret_cast<uint32_t*>(&C[(size_t)(row + 8) * N_real + col]) =
                        *reinterpret_cast<uint32_t*>(&p1);
                } else {
                    const float DS = 1.0f / 4096.0f;
                    float2 v0 = make_float2(acc[i][j][0] * DS, acc[i][j][1] * DS);
                    float2 v1 = make_float2(acc[i][j][2] * DS, acc[i][j][3] * DS);
                    *reinterpret_cast<float2*>(&C[(size_t)row * N_real + col]) = v0;
                    *reinterpret_cast<float2*>(&C[(size_t)(row + 8) * N_real + col]) = v1;
                }
            }
        }
    }
#undef LOAD_STAGE
}

// ---------------- flash attention via mma.sync fp16 (MQA, causal) ------------
#define FROW_B 144
#define QARR_B (128 * FROW_B)
#define KV_STG (2 * QARR_B)                 // K, V
#define FA_SMEM (QARR_B + 2 * KV_STG)       // 92160

__global__ __launch_bounds__(256, 1) void flash_mma(
    const __half* __restrict__ qh,
    const __half* __restrict__ kh, const __half* __restrict__ vh,
    __half* __restrict__ oh)
{
    extern __shared__ __align__(128) char smem[];
    const int tid = threadIdx.x, wid = tid >> 5, lid = tid & 31;
    const int qt = (int)gridDim.x - 1 - blockIdx.x;   // long blocks first
    const int h  = blockIdx.y;
    const int q0 = qt * 128;
    const uint32_t sb = smem_to_u32(smem);
    const uint32_t sQ  = sb;
    const uint32_t sKV = sb + QARR_B;

    {
        #pragma unroll
        for (int i = 0; i < 4; i++) {
            int id = i * 256 + tid;
            int r = id >> 3, c = id & 7;
            cp_async16(sQ + r * FROW_B + c * 16,
                       qh + ((size_t)h * SEQ + q0 + r) * HD + c * 8);
        }
    }
    const __half* kvsrc[2] = {kh, vh};
#define LOAD_KV(s, kt_) do {                                                   \
        _Pragma("unroll")                                                      \
        for (int i_ = 0; i_ < 8; i_++) {                                       \
            int id_ = i_ * 256 + tid;                                          \
            int a_ = id_ >> 10, w_ = id_ & 1023, r_ = w_ >> 3, c_ = w_ & 7;    \
            cp_async16(sKV + (s) * KV_STG + a_ * QARR_B + r_ * FROW_B + c_ * 16, \
                       kvsrc[a_] + ((size_t)((kt_) * 128 + r_)) * HD + c_ * 8); \
        }                                                                      \
    } while (0)
    LOAD_KV(0, 0);
    CP_COMMIT();
    CP_WAIT(0);
    __syncthreads();

    const int arow  = (lid & 7) | (((lid >> 3) & 1) << 3);
    const int acolh = (lid >> 4) * 8;
    const int brow  = (lid & 7) + ((lid >> 4) & 1) * 8;
    const int bcolh = ((lid >> 3) & 1) * 8;

    uint32_t aq[4][4];
    #pragma unroll
    for (int k = 0; k < 4; k++) {
        uint32_t off = (uint32_t)((wid * 16 + arow) * FROW_B + (k * 16 + acolh) * 2);
        ldsm_x4(aq[k][0], aq[k][1], aq[k][2], aq[k][3], sQ + off);
    }

    float acc[8][4];
    #pragma unroll
    for (int g = 0; g < 8; g++)
        #pragma unroll
        for (int e = 0; e < 4; e++) acc[g][e] = 0.0f;
    float m0 = -1e30f, m1 = -1e30f, l0 = 0.0f, l1 = 0.0f;
    const int row0 = q0 + wid * 16 + (lid >> 2);
    const float SC = 1.0f / 16384.0f;   // undo 32*64 q/k scaling (incl 1/8)

    const int nkv = qt + 1;
    for (int kt = 0; kt < nkv; kt++) {
        const int cur = kt & 1;
        if (kt + 1 < nkv) { LOAD_KV(cur ^ 1, kt + 1); CP_COMMIT(); }
        const uint32_t sK = sKV + cur * KV_STG;
        const uint32_t sV = sK + QARR_B;

        float sc[16][4];
        #pragma unroll
        for (int t = 0; t < 16; t++)
            #pragma unroll
            for (int e = 0; e < 4; e++) sc[t][e] = 0.0f;

        #pragma unroll
        for (int j2 = 0; j2 < 8; j2++) {
            #pragma unroll
            for (int k = 0; k < 4; k++) {
                uint32_t off = (uint32_t)((j2 * 16 + brow) * FROW_B + (k * 16 + bcolh) * 2);
                uint32_t b0, b1, b2, b3;
                ldsm_x4(b0, b1, b2, b3, sK + off);
                mma16816(sc[j2 * 2],     aq[k], b0, b1);
                mma16816(sc[j2 * 2 + 1], aq[k], b2, b3);
            }
        }

        #pragma unroll
        for (int t = 0; t < 16; t++)
            #pragma unroll
            for (int e = 0; e < 4; e++) sc[t][e] *= SC;

        if (kt == qt) {
            #pragma unroll
            for (int t = 0; t < 16; t++) {
                int colb = kt * 128 + t * 8 + (lid & 3) * 2;
                if (colb     > row0)     sc[t][0] = -1e30f;
                if (colb + 1 > row0)     sc[t][1] = -1e30f;
                if (colb     > row0 + 8) sc[t][2] = -1e30f;
                if (colb + 1 > row0 + 8) sc[t][3] = -1e30f;
            }
        }

        float mn0 = m0, mn1 = m1;
        #pragma unroll
        for (int t = 0; t < 16; t++) {
            mn0 = fmaxf(mn0, fmaxf(sc[t][0], sc[t][1]));
            mn1 = fmaxf(mn1, fmaxf(sc[t][2], sc[t][3]));
        }
        mn0 = fmaxf(mn0, __shfl_xor_sync(0xffffffffu, mn0, 1));
        mn0 = fmaxf(mn0, __shfl_xor_sync(0xffffffffu, mn0, 2));
        mn1 = fmaxf(mn1, __shfl_xor_sync(0xffffffffu, mn1, 1));
        mn1 = fmaxf(mn1, __shfl_xor_sync(0xffffffffu, mn1, 2));
        float corr0 = __expf(m0 - mn0);
        float corr1 = __expf(m1 - mn1);

        uint32_t phi[16][2];
        float ls0 = 0.0f, ls1 = 0.0f;
        #pragma unroll
        for (int t = 0; t < 16; t++) {
            float p0 = __expf(sc[t][0] - mn0);
            float p1 = __expf(sc[t][1] - mn0);
            float p2 = __expf(sc[t][2] - mn1);
            float p3 = __expf(sc[t][3] - mn1);
            ls0 += p0 + p1;  ls1 += p2 + p3;
            __half2 ph0 = __floats2half2_rn(p0 * 64.f, p1 * 64.f);
            __half2 ph1 = __floats2half2_rn(p2 * 64.f, p3 * 64.f);
            phi[t][0] = *reinterpret_cast<uint32_t*>(&ph0);
            phi[t][1] = *reinterpret_cast<uint32_t*>(&ph1);
        }
        ls0 += __shfl_xor_sync(0xffffffffu, ls0, 1);
        ls0 += __shfl_xor_sync(0xffffffffu, ls0, 2);
        ls1 += __shfl_xor_sync(0xffffffffu, ls1, 1);
        ls1 += __shfl_xor_sync(0xffffffffu, ls1, 2);
        l0 = l0 * corr0 + ls0;  l1 = l1 * corr1 + ls1;
        m0 = mn0;  m1 = mn1;
        #pragma unroll
        for (int g = 0; g < 8; g++) {
            acc[g][0] *= corr0; acc[g][1] *= corr0;
            acc[g][2] *= corr1; acc[g][3] *= corr1;
        }

        #pragma unroll
        for (int k = 0; k < 8; k++) {
            uint32_t ph_[4] = {phi[k * 2][0], phi[k * 2][1], phi[k * 2 + 1][0], phi[k * 2 + 1][1]};
            #pragma unroll
            for (int g = 0; g < 4; g++) {
                uint32_t off = (uint32_t)((k * 16 + (lid & 15)) * FROW_B +
                                          (g * 16 + ((lid >> 4) & 1) * 8) * 2);
                uint32_t v0, v1, v2, v3;
                ldsm_x4_t(v0, v1, v2, v3, sV + off);
                mma16816(acc[g * 2],     ph_, v0, v1);
                mma16816(acc[g * 2 + 1], ph_, v2, v3);
            }
        }

        if (kt + 1 < nkv) CP_WAIT(0);
        __syncthreads();
    }
#undef LOAD_KV

    // out' = 64 * true_out: acc = 4096*(P.V)/64-scales, /l, *64
    float inv0 = 1.0f / (64.0f * l0), inv1 = 1.0f / (64.0f * l1);
    #pragma unroll
    for (int g = 0; g < 8; g++) {
        int col = h * HD + g * 8 + (lid & 3) * 2;
        int r = q0 + wid * 16 + (lid >> 2);
        __half2 h0 = __floats2half2_rn(acc[g][0] * inv0, acc[g][1] * inv0);
        __half2 h1 = __floats2half2_rn(acc[g][2] * inv1, acc[g][3] * inv1);
        *reinterpret_cast<uint32_t*>(&oh[(size_t)r * QDIM + col]) =
            *reinterpret_cast<uint32_t*>(&h0);
        *reinterpret_cast<uint32_t*>(&oh[(size_t)(r + 8) * QDIM + col]) =
            *reinterpret_cast<uint32_t*>(&h1);
    }
}

// ---------------- launch ----------------------------------------------------
extern "C" void kernel_launch(void* const* d_in, const int* in_sizes, int n_in,
                              void* d_out, int out_size)
{
    const float* x       = (const float*)d_in[0];
    const float* qkv_w   = (const float*)d_in[1];
    const float* dense_w = (const float*)d_in[2];
    float* out = (float*)d_out;

    __half *fusedh, *xh, *wqh, *wdh, *ah, *qsh, *ksh, *vsh;
    cudaGetSymbolAddress((void**)&fusedh, g_fused_h);
    cudaGetSymbolAddress((void**)&xh,  g_xh);
    cudaGetSymbolAddress((void**)&wqh, g_wqh);
    cudaGetSymbolAddress((void**)&wdh, g_wdh);
    cudaGetSymbolAddress((void**)&ah,  g_ah);
    cudaGetSymbolAddress((void**)&qsh, g_qsh);
    cudaGetSymbolAddress((void**)&ksh, g_ksh);
    cudaGetSymbolAddress((void**)&vsh, g_vsh);

    cudaFuncSetAttribute(gemm_mma<__half>,
                         cudaFuncAttributeMaxDynamicSharedMemorySize, GEMM_SMEM);
    cudaFuncSetAttribute(gemm_mma<float>,
                         cudaFuncAttributeMaxDynamicSharedMemorySize, GEMM_SMEM);
    cudaFuncSetAttribute(flash_mma,
                         cudaFuncAttributeMaxDynamicSharedMemorySize, FA_SMEM);

    // 1. RoPE table
    rope_table_kernel<<<(SEQ * 32 + 255) / 256, 256>>>();

    // 2. fp16 conversions (x64 scale), single merged launch
    {
        int n0 = SEQ * HIDDEN / 4;
        int n1 = QKV_PAD * HIDDEN / 4, s1 = QKV_OUT * HIDDEN / 4;
        int n2 = DEN_PAD * HIDDEN / 4, s2 = HIDDEN * HIDDEN / 4;
        int total = n0 + n1 + n2;
        convert_all<<<(total + 255) / 256, 256>>>(
            (const float4*)x, (const float4*)qkv_w, (const float4*)dense_w,
            (uint2*)xh, (uint2*)wqh, (uint2*)wdh, n0, n1, n2, s1, s2);
    }

    // 3. QKV GEMM -> half fused (x64)
    {
        dim3 grid(QKV_PAD / BN2, SEQ / BM2);
        gemm_mma<__half><<<grid, 512, GEMM_SMEM>>>(xh, wqh, fusedh,
                                                   QKV_OUT, HIDDEN);
    }

    // 4. prep: rope + scale + fp16 of q, k, v
    {
        int total = SEQ * (NH + 2) * 32;
        prep_kernel<<<(total + 255) / 256, 256>>>();
    }

    // 5. flash attention -> fp16 activations (x64), long blocks first
    {
        dim3 grid(SEQ / 128, NH);
        flash_mma<<<grid, 256, FA_SMEM>>>(qsh, ksh, vsh, ah);
    }

    // 6. dense GEMM -> fp32 out
    {
        dim3 grid(DEN_PAD / BN2, SEQ / BM2);
        gemm_mma<float><<<grid, 512, GEMM_SMEM>>>(ah, wdh, out, HIDDEN, HIDDEN);
    }
}